// round 8
// baseline (speedup 1.0000x reference)
#include <cuda_runtime.h>
#include <cuda_fp16.h>
#include <cstdint>

#define NN 50000
#define D  128
#define NE 800000
#define NL 200000

// ---------------- scratch ----------------------------------------------------
__device__ __half g_h0h[NN * D];
__device__ __half g_h1h[NN * D];
__device__ __half g_h2h[NN * D];
__device__ int    g_deg[NN];
__device__ int    g_rowptr[NN];
__device__ int    g_cursor[NN];
__device__ int    g_col[NE];
__device__ int    g_bsums[64];
// B fragments (fp16): [layer(2)][kstep(16)][ntile(16)][lane(32)] x uint2{b0,b1}
__device__ uint2  g_bfrag[2 * 16 * 16 * 32];

// ---------------- helpers -----------------------------------------------------
__device__ __forceinline__ uint32_t su32(const void* p) {
    uint32_t a;
    asm("{ .reg .u64 t; cvta.to.shared.u64 t, %1; cvt.u32.u64 %0, t; }"
        : "=r"(a) : "l"(p));
    return a;
}

#define LDSM4(r, addr) \
    asm volatile("ldmatrix.sync.aligned.m8n8.x4.shared.b16 {%0,%1,%2,%3}, [%4];" \
                 : "=r"((r)[0]), "=r"((r)[1]), "=r"((r)[2]), "=r"((r)[3]) : "r"(addr))

#define MMA_F16(d, a, b) \
    asm volatile("mma.sync.aligned.m16n8k16.row.col.f32.f16.f16.f32 " \
                 "{%0,%1,%2,%3},{%4,%5,%6,%7},{%8,%9},{%0,%1,%2,%3};" \
                 : "+f"((d)[0]), "+f"((d)[1]), "+f"((d)[2]), "+f"((d)[3]) \
                 : "r"((a)[0]), "r"((a)[1]), "r"((a)[2]), "r"((a)[3]), \
                   "r"((b)[0]), "r"((b)[1]))

// ---------------- fused prologue: concat + degree(4x ILP) + wfrag ------------
#define CB 6250   // concat blocks: NN*32/256
#define DB 782    // degree blocks: NE/4/256 (4 edges per thread)
#define WB 64     // wfrag blocks: 16384/256

__global__ void k_pre(const int* __restrict__ n_id,
                      const float* __restrict__ x,
                      const float* __restrict__ emb,
                      const int* __restrict__ dst,
                      const float* __restrict__ W1l, const float* __restrict__ W1r,
                      const float* __restrict__ W2l, const float* __restrict__ W2r,
                      __half* __restrict__ h0h,
                      int* __restrict__ deg, uint2* __restrict__ bf) {
    int b = blockIdx.x;
    if (b < CB) {
        int t = b * 256 + threadIdx.x;
        int i = t >> 5;
        int q = t & 31;
        float4 v;
        if (q < 16) v = *(const float4*)&emb[(long)n_id[i] * 64 + q * 4];
        else        v = *(const float4*)&x[(long)i * 64 + (q - 16) * 4];
        __half2 p0 = __floats2half2_rn(v.x, v.y);
        __half2 p1 = __floats2half2_rn(v.z, v.w);
        uint2 pk = make_uint2(*(uint32_t*)&p0, *(uint32_t*)&p1);
        *(uint2*)&h0h[(long)i * 128 + q * 4] = pk;
    } else if (b < CB + DB) {
        int e0 = ((b - CB) * 256 + threadIdx.x) * 4;
        if (e0 < NE) {
            int4 d4 = *(const int4*)&dst[e0];
            atomicAdd(&deg[d4.x], 1);
            atomicAdd(&deg[d4.y], 1);
            atomicAdd(&deg[d4.z], 1);
            atomicAdd(&deg[d4.w], 1);
        }
    } else {
        int t = (b - CB - DB) * 256 + threadIdx.x;
        if (t < 2 * 16 * 16 * 32) {
            int L    = t >> 13;
            int s    = (t >> 9) & 15;
            int n    = (t >> 5) & 15;
            int lane = t & 31;
            int gid = lane >> 2, tig = lane & 3;
            int col = n * 8 + gid;
            const float* Wl = L ? W2l : W1l;
            const float* Wr = L ? W2r : W1r;
            uint32_t bb[2];
#pragma unroll
            for (int r = 0; r < 2; r++) {
                int k0 = s * 16 + r * 8 + 2 * tig;
                float v0 = (k0     < 128) ? Wl[k0 * 128 + col]       : Wr[(k0 - 128) * 128 + col];
                float v1 = (k0 + 1 < 128) ? Wl[(k0 + 1) * 128 + col] : Wr[(k0 + 1 - 128) * 128 + col];
                __half2 p = __floats2half2_rn(v0, v1);
                bb[r] = *(uint32_t*)&p;
            }
            bf[t] = make_uint2(bb[0], bb[1]);
        }
    }
}

// ---------------- CSR build ---------------------------------------------------
__global__ void k_scan1(const int* __restrict__ deg, int* __restrict__ out,
                        int* __restrict__ bsums, int* __restrict__ cursor) {
    __shared__ int sh[1024];
    int gid = blockIdx.x * 1024 + threadIdx.x;
    int v = (gid < NN) ? deg[gid] : 0;
    sh[threadIdx.x] = v;
    __syncthreads();
#pragma unroll
    for (int off = 1; off < 1024; off <<= 1) {
        int t = (threadIdx.x >= off) ? sh[threadIdx.x - off] : 0;
        __syncthreads();
        sh[threadIdx.x] += t;
        __syncthreads();
    }
    if (gid < NN) {
        out[gid]    = sh[threadIdx.x] - v;
        cursor[gid] = 0;
    }
    if (threadIdx.x == 1023) bsums[blockIdx.x] = sh[1023];
}

__global__ void k_scan3f(int* __restrict__ out, const int* __restrict__ bsums, int nb) {
    __shared__ int sh[64];
    int t = threadIdx.x;
    if (t < 32) {
        int v0 = (t      < nb) ? bsums[t]      : 0;
        int v1 = (t + 32 < nb) ? bsums[t + 32] : 0;
#pragma unroll
        for (int off = 1; off < 32; off <<= 1) {
            int u0 = __shfl_up_sync(0xffffffffu, v0, off);
            int u1 = __shfl_up_sync(0xffffffffu, v1, off);
            if ((int)t >= off) { v0 += u0; v1 += u1; }
        }
        int tot0 = __shfl_sync(0xffffffffu, v0, 31);
        sh[t]      = v0;
        sh[t + 32] = v1 + tot0;
    }
    __syncthreads();
    int offv = (blockIdx.x == 0) ? 0 : sh[blockIdx.x - 1];
    int gid = blockIdx.x * 1024 + t;
    if (gid < NN) out[gid] += offv;
}

// 4 edges per thread for MLP on the rowptr-gather + atomic chain
__global__ void k_fill(const int* __restrict__ src, const int* __restrict__ dst,
                       const int* __restrict__ rowptr, int* __restrict__ cursor,
                       int* __restrict__ col) {
    int e0 = (blockIdx.x * blockDim.x + threadIdx.x) * 4;
    if (e0 >= NE) return;
    int4 d4 = *(const int4*)&dst[e0];
    int4 s4 = *(const int4*)&src[e0];
    int r0 = rowptr[d4.x];
    int r1 = rowptr[d4.y];
    int r2 = rowptr[d4.z];
    int r3 = rowptr[d4.w];
    int p0 = r0 + atomicAdd(&cursor[d4.x], 1);
    int p1 = r1 + atomicAdd(&cursor[d4.y], 1);
    int p2 = r2 + atomicAdd(&cursor[d4.z], 1);
    int p3 = r3 + atomicAdd(&cursor[d4.w], 1);
    col[p0] = s4.x;
    col[p1] = s4.y;
    col[p2] = s4.z;
    col[p3] = s4.w;
}

// ---------------- fused SAGE layer: gather-mean + fp16 mma GEMM --------------
// out16[M,128] = [mean16 | h16](K=256 fp16) @ Wfp16 + b
// Phase 1: 8 warps gather/mean 128 nodes into 4 smem A-planes (mma layout).
// Phase 2: chunks 0-3 read sMean planes; chunks 4-7 stage h16 double-buffered.
#define APITCH 40                      // halfwords per row
#define PLANE  (128 * APITCH * 2)      // 10240 bytes
#define SMEM_SAGE (6 * PLANE)          // 4 mean planes + 2 staging buffers

__global__ void __launch_bounds__(256, 2)
k_sage(const __half* __restrict__ H16,
       const int* __restrict__ rowptr, const int* __restrict__ deg,
       const int* __restrict__ colidx,
       const uint2* __restrict__ Bf, const float* __restrict__ bias,
       __half* __restrict__ outh, int do_relu) {
    extern __shared__ __align__(16) uint8_t dsm[];
    uint8_t* sMean = dsm;                 // 4 planes (chunks 0-3 of A)
    uint8_t* sAb   = dsm + 4 * PLANE;     // 2 staging buffers (chunks 4-7)

    int tid  = threadIdx.x;
    int wid  = tid >> 5;
    int lane = tid & 31;
    int wm   = wid & 3;
    int wn   = wid >> 2;
    int gid  = lane >> 2, tig = lane & 3;
    int row0 = blockIdx.x * 128;

    int laneRow = lane & 15;
    int laneKo  = (lane >> 4) * 8;

    // ---- phase 1: gather + mean into sMean planes ----
    {
        const uint2* hp = (const uint2*)H16;
        int planeSel = lane >> 3;                 // which 32-k chunk this lane's 4 elems live in
        int laneOff  = (lane & 7) * 8;            // byte offset within row of that plane
        for (int r = wid; r < 128; r += 8) {
            int node = row0 + r;
            float4 acc = make_float4(0.f, 0.f, 0.f, 0.f);
            int n = 0;
            if (node < NN) {
                int start = rowptr[node];
                n = deg[node];
                int j = 0;
                for (; j + 4 <= n; j += 4) {
                    int s0 = colidx[start + j];
                    int s1 = colidx[start + j + 1];
                    int s2 = colidx[start + j + 2];
                    int s3 = colidx[start + j + 3];
                    uint2 v0 = hp[(long)s0 * 32 + lane];
                    uint2 v1 = hp[(long)s1 * 32 + lane];
                    uint2 v2 = hp[(long)s2 * 32 + lane];
                    uint2 v3 = hp[(long)s3 * 32 + lane];
#pragma unroll
                    for (int u = 0; u < 4; u++) {
                        uint2 raw = (u == 0) ? v0 : (u == 1) ? v1 : (u == 2) ? v2 : v3;
                        float2 a = __half22float2(*(const __half2*)&raw.x);
                        float2 b = __half22float2(*(const __half2*)&raw.y);
                        acc.x += a.x; acc.y += a.y; acc.z += b.x; acc.w += b.y;
                    }
                }
                for (; j < n; j++) {
                    int s = colidx[start + j];
                    uint2 raw = hp[(long)s * 32 + lane];
                    float2 a = __half22float2(*(const __half2*)&raw.x);
                    float2 b = __half22float2(*(const __half2*)&raw.y);
                    acc.x += a.x; acc.y += a.y; acc.z += b.x; acc.w += b.y;
                }
            }
            float inv = 1.0f / fmaxf((float)n, 1.0f);
            __half2 p0 = __floats2half2_rn(acc.x * inv, acc.y * inv);
            __half2 p1 = __floats2half2_rn(acc.z * inv, acc.w * inv);
            uint2 pk = make_uint2(*(uint32_t*)&p0, *(uint32_t*)&p1);
            *(uint2*)&sMean[planeSel * PLANE + r * (APITCH * 2) + laneOff] = pk;
        }
    }

    float acc[2][8][4];
#pragma unroll
    for (int mt = 0; mt < 2; mt++)
#pragma unroll
        for (int nt = 0; nt < 8; nt++)
#pragma unroll
            for (int j = 0; j < 4; j++) acc[mt][nt][j] = 0.f;

    const uint4 z4 = make_uint4(0u, 0u, 0u, 0u);
    int srow = tid >> 1;          // staging row (0..127)
    int sseg = tid & 1;           // 16-half segment

    // stage chunk 4 (first h16 chunk) into sAb[0]
    {
        int gr = row0 + srow;
        uint4 v0 = z4, v1 = z4;
        if (gr < NN) {
            const uint4* src = (const uint4*)&H16[(long)gr * 128 + sseg * 16];
            v0 = src[0];
            v1 = src[1];
        }
        int off = srow * (APITCH * 2) + sseg * 32;
        *(uint4*)&sAb[off]      = v0;
        *(uint4*)&sAb[off + 16] = v1;
    }
    __syncthreads();   // covers phase-1 writes AND chunk-4 staging

    uint32_t meanBase = su32(sMean);
    uint32_t abBase   = su32(sAb);

#pragma unroll 1
    for (int c = 0; c < 8; ++c) {
        // prefetch next h16 chunk (for c >= 4 region)
        uint4 p0 = z4, p1 = z4;
        if (c >= 4 && c < 7) {
            int bk = (c + 1 - 4) * 32;
            int gr = row0 + srow;
            if (gr < NN) {
                const uint4* src = (const uint4*)&H16[(long)gr * 128 + bk + sseg * 16];
                p0 = src[0];
                p1 = src[1];
            }
        }

        uint32_t aBase = (c < 4) ? (meanBase + (uint32_t)(c * PLANE))
                                 : (abBase + (uint32_t)(((c - 4) & 1) * PLANE));
#pragma unroll
        for (int ks = 0; ks < 2; ks++) {
            int s = c * 2 + ks;
            uint32_t af[2][4];
#pragma unroll
            for (int mt = 0; mt < 2; mt++) {
                uint32_t addr = aBase
                    + (uint32_t)((wm * 32 + mt * 16 + laneRow) * (APITCH * 2)
                                 + (ks * 16 + laneKo) * 2);
                LDSM4(af[mt], addr);
            }
            uint2 bfr[8];
#pragma unroll
            for (int nt = 0; nt < 8; nt++)
                bfr[nt] = __ldg(&Bf[(s * 16 + wn * 8 + nt) * 32 + lane]);
#pragma unroll
            for (int nt = 0; nt < 8; nt++) {
                uint32_t bb[2] = {bfr[nt].x, bfr[nt].y};
#pragma unroll
                for (int mt = 0; mt < 2; mt++)
                    MMA_F16(acc[mt][nt], af[mt], bb);
            }
        }

        // store prefetched chunk into the other staging buffer
        if (c >= 4 && c < 7) {
            __syncthreads();   // buffer we're about to overwrite was consumed this iter? no — next buffer
            int nb = (c + 1 - 4) & 1;
            int off = srow * (APITCH * 2) + sseg * 32;
            *(uint4*)&sAb[nb * PLANE + off]      = p0;
            *(uint4*)&sAb[nb * PLANE + off + 16] = p1;
            __syncthreads();
        }
    }

    // ---- epilogue: fp16 out ----
#pragma unroll
    for (int mt = 0; mt < 2; mt++) {
        int r0 = row0 + wm * 32 + mt * 16 + gid;
        int r1 = r0 + 8;
#pragma unroll
        for (int nt = 0; nt < 8; nt++) {
            int cbase = wn * 64 + nt * 8 + tig * 2;
            float bx = __ldg(&bias[cbase]);
            float by = __ldg(&bias[cbase + 1]);
            float2 v0 = make_float2(acc[mt][nt][0] + bx, acc[mt][nt][1] + by);
            float2 v1 = make_float2(acc[mt][nt][2] + bx, acc[mt][nt][3] + by);
            if (do_relu) {
                v0.x = fmaxf(v0.x, 0.f); v0.y = fmaxf(v0.y, 0.f);
                v1.x = fmaxf(v1.x, 0.f); v1.y = fmaxf(v1.y, 0.f);
            }
            __half2 h0p = __floats2half2_rn(v0.x, v0.y);
            __half2 h1p = __floats2half2_rn(v1.x, v1.y);
            if (r0 < NN) *(uint32_t*)&outh[(long)r0 * 128 + cbase] = *(uint32_t*)&h0p;
            if (r1 < NN) *(uint32_t*)&outh[(long)r1 * 128 + cbase] = *(uint32_t*)&h1p;
        }
    }
}

// ---------------- edge-wise dot product (fp16 gather) -------------------------
__global__ void k_edgedot(const __half* __restrict__ h16,
                          const int* __restrict__ eli,
                          float* __restrict__ out) {
    int w    = (blockIdx.x * blockDim.x + threadIdx.x) >> 5;
    int lane = threadIdx.x & 31;
    if (w >= NL) return;
    int s = eli[w];
    int d = eli[NL + w];
    const uint2* hp = (const uint2*)h16;
    uint2 ra = hp[(long)s * 32 + lane];
    uint2 rb = hp[(long)d * 32 + lane];
    float2 a0 = __half22float2(*(const __half2*)&ra.x);
    float2 a1 = __half22float2(*(const __half2*)&ra.y);
    float2 b0 = __half22float2(*(const __half2*)&rb.x);
    float2 b1 = __half22float2(*(const __half2*)&rb.y);
    float sum = a0.x * b0.x + a0.y * b0.y + a1.x * b1.x + a1.y * b1.y;
#pragma unroll
    for (int o = 16; o; o >>= 1) sum += __shfl_xor_sync(0xffffffffu, sum, o);
    if (lane == 0) out[w] = sum;
}

// ---------------- launch ------------------------------------------------------
extern "C" void kernel_launch(void* const* d_in, const int* in_sizes, int n_in,
                              void* d_out, int out_size) {
    const int*   n_id = (const int*)d_in[0];
    const float* x    = (const float*)d_in[1];
    const int*   ei   = (const int*)d_in[2];
    const int*   eli  = (const int*)d_in[3];
    const float* emb  = (const float*)d_in[4];
    const float* W1l  = (const float*)d_in[5];
    const float* W1r  = (const float*)d_in[6];
    const float* b1   = (const float*)d_in[7];
    const float* W2l  = (const float*)d_in[8];
    const float* W2r  = (const float*)d_in[9];
    const float* b2   = (const float*)d_in[10];
    float* out = (float*)d_out;

    __half *h0h, *h1h, *h2h;
    int *deg, *rowptr, *cursor, *col, *bsums;
    uint2* bfrag;
    cudaGetSymbolAddress((void**)&h0h,    g_h0h);
    cudaGetSymbolAddress((void**)&h1h,    g_h1h);
    cudaGetSymbolAddress((void**)&h2h,    g_h2h);
    cudaGetSymbolAddress((void**)&deg,    g_deg);
    cudaGetSymbolAddress((void**)&rowptr, g_rowptr);
    cudaGetSymbolAddress((void**)&cursor, g_cursor);
    cudaGetSymbolAddress((void**)&col,    g_col);
    cudaGetSymbolAddress((void**)&bsums,  g_bsums);
    cudaGetSymbolAddress((void**)&bfrag,  g_bfrag);

    cudaFuncSetAttribute(k_sage, cudaFuncAttributeMaxDynamicSharedMemorySize, SMEM_SAGE);

    const int NB_SCAN = (NN + 1023) / 1024;  // 49

    cudaMemsetAsync(deg, 0, sizeof(int) * NN);

    k_pre<<<CB + DB + WB, 256>>>(n_id, x, emb, ei + NE, W1l, W1r, W2l, W2r,
                                 h0h, deg, bfrag);
    k_scan1<<<NB_SCAN, 1024>>>(deg, rowptr, bsums, cursor);
    k_scan3f<<<NB_SCAN, 1024>>>(rowptr, bsums, NB_SCAN);
    k_fill<<<(NE / 4 + 255) / 256, 256>>>(ei, ei + NE, rowptr, cursor, col);

    const int GB = (NN + 127) / 128;  // 391

    // layer 1 (fused agg + gemm)
    k_sage<<<GB, 256, SMEM_SAGE>>>(h0h, rowptr, deg, col, bfrag, b1, h1h, 1);
    // layer 2
    k_sage<<<GB, 256, SMEM_SAGE>>>(h1h, rowptr, deg, col, bfrag + 8192, b2, h2h, 0);

    // classifier
    k_edgedot<<<(NL * 32 + 255) / 256, 256>>>(h2h, eli, out);
}

// round 9
// speedup vs baseline: 1.2706x; 1.2706x over previous
#include <cuda_runtime.h>
#include <cuda_fp16.h>
#include <cstdint>

#define NN 50000
#define D  128
#define NE 800000
#define NL 200000

// ---------------- scratch ----------------------------------------------------
__device__ __half g_h0h[NN * D];
__device__ __half g_mean16[NN * D];
__device__ __half g_h1h[NN * D];
__device__ __half g_h2h[NN * D];
__device__ int    g_deg[NN];
__device__ int    g_rowptr[NN];
__device__ int    g_cursor[NN];
__device__ int    g_col[NE];
__device__ int    g_bsums[64];
// B fragments (fp16): [layer(2)][kstep(16)][ntile(16)][lane(32)] x uint2{b0,b1}
__device__ uint2  g_bfrag[2 * 16 * 16 * 32];

// ---------------- helpers -----------------------------------------------------
__device__ __forceinline__ uint32_t su32(const void* p) {
    uint32_t a;
    asm("{ .reg .u64 t; cvta.to.shared.u64 t, %1; cvt.u32.u64 %0, t; }"
        : "=r"(a) : "l"(p));
    return a;
}

#define LDSM4(r, addr) \
    asm volatile("ldmatrix.sync.aligned.m8n8.x4.shared.b16 {%0,%1,%2,%3}, [%4];" \
                 : "=r"((r)[0]), "=r"((r)[1]), "=r"((r)[2]), "=r"((r)[3]) : "r"(addr))

#define MMA_F16(d, a, b) \
    asm volatile("mma.sync.aligned.m16n8k16.row.col.f32.f16.f16.f32 " \
                 "{%0,%1,%2,%3},{%4,%5,%6,%7},{%8,%9},{%0,%1,%2,%3};" \
                 : "+f"((d)[0]), "+f"((d)[1]), "+f"((d)[2]), "+f"((d)[3]) \
                 : "r"((a)[0]), "r"((a)[1]), "r"((a)[2]), "r"((a)[3]), \
                   "r"((b)[0]), "r"((b)[1]))

// ---------------- fused prologue: concat + degree + wfrag --------------------
#define CB 6250   // concat blocks: NN*32/256
#define DB 3125   // degree blocks: NE/256
#define WB 64     // wfrag blocks: 16384/256

__global__ void k_pre(const int* __restrict__ n_id,
                      const float* __restrict__ x,
                      const float* __restrict__ emb,
                      const int* __restrict__ dst,
                      const float* __restrict__ W1l, const float* __restrict__ W1r,
                      const float* __restrict__ W2l, const float* __restrict__ W2r,
                      __half* __restrict__ h0h,
                      int* __restrict__ deg, uint2* __restrict__ bf) {
    int b = blockIdx.x;
    if (b < CB) {
        int t = b * 256 + threadIdx.x;
        int i = t >> 5;
        int q = t & 31;
        float4 v;
        if (q < 16) v = *(const float4*)&emb[(long)n_id[i] * 64 + q * 4];
        else        v = *(const float4*)&x[(long)i * 64 + (q - 16) * 4];
        __half2 p0 = __floats2half2_rn(v.x, v.y);
        __half2 p1 = __floats2half2_rn(v.z, v.w);
        uint2 pk = make_uint2(*(uint32_t*)&p0, *(uint32_t*)&p1);
        *(uint2*)&h0h[(long)i * 128 + q * 4] = pk;
    } else if (b < CB + DB) {
        int e = (b - CB) * 256 + threadIdx.x;
        if (e < NE) atomicAdd(&deg[dst[e]], 1);
    } else {
        int t = (b - CB - DB) * 256 + threadIdx.x;
        if (t < 2 * 16 * 16 * 32) {
            int L    = t >> 13;
            int s    = (t >> 9) & 15;
            int n    = (t >> 5) & 15;
            int lane = t & 31;
            int gid = lane >> 2, tig = lane & 3;
            int col = n * 8 + gid;
            const float* Wl = L ? W2l : W1l;
            const float* Wr = L ? W2r : W1r;
            uint32_t bb[2];
#pragma unroll
            for (int r = 0; r < 2; r++) {
                int k0 = s * 16 + r * 8 + 2 * tig;
                float v0 = (k0     < 128) ? Wl[k0 * 128 + col]       : Wr[(k0 - 128) * 128 + col];
                float v1 = (k0 + 1 < 128) ? Wl[(k0 + 1) * 128 + col] : Wr[(k0 + 1 - 128) * 128 + col];
                __half2 p = __floats2half2_rn(v0, v1);
                bb[r] = *(uint32_t*)&p;
            }
            bf[t] = make_uint2(bb[0], bb[1]);
        }
    }
}

// ---------------- CSR build ---------------------------------------------------
__global__ void k_scan1(const int* __restrict__ deg, int* __restrict__ out,
                        int* __restrict__ bsums) {
    __shared__ int sh[1024];
    int gid = blockIdx.x * 1024 + threadIdx.x;
    int v = (gid < NN) ? deg[gid] : 0;
    sh[threadIdx.x] = v;
    __syncthreads();
#pragma unroll
    for (int off = 1; off < 1024; off <<= 1) {
        int t = (threadIdx.x >= off) ? sh[threadIdx.x - off] : 0;
        __syncthreads();
        sh[threadIdx.x] += t;
        __syncthreads();
    }
    if (gid < NN) out[gid] = sh[threadIdx.x] - v;
    if (threadIdx.x == 1023) bsums[blockIdx.x] = sh[1023];
}

// fused scan2+scan3 + cursor init (cursor starts at final rowptr)
__global__ void k_scan3f(int* __restrict__ out, const int* __restrict__ bsums,
                         int nb, int* __restrict__ cursor) {
    __shared__ int sh[64];
    int t = threadIdx.x;
    if (t < 32) {
        int v0 = (t      < nb) ? bsums[t]      : 0;
        int v1 = (t + 32 < nb) ? bsums[t + 32] : 0;
#pragma unroll
        for (int off = 1; off < 32; off <<= 1) {
            int u0 = __shfl_up_sync(0xffffffffu, v0, off);
            int u1 = __shfl_up_sync(0xffffffffu, v1, off);
            if ((int)t >= off) { v0 += u0; v1 += u1; }
        }
        int tot0 = __shfl_sync(0xffffffffu, v0, 31);
        sh[t]      = v0;
        sh[t + 32] = v1 + tot0;
    }
    __syncthreads();
    int offv = (blockIdx.x == 0) ? 0 : sh[blockIdx.x - 1];
    int gid = blockIdx.x * 1024 + t;
    if (gid < NN) {
        int rp = out[gid] + offv;
        out[gid]    = rp;
        cursor[gid] = rp;      // fill uses cursor directly (no rowptr load)
    }
}

// 1 edge/thread; cursor pre-initialized to rowptr
__global__ void k_fill(const int* __restrict__ src, const int* __restrict__ dst,
                       int* __restrict__ cursor, int* __restrict__ col) {
    int e = blockIdx.x * blockDim.x + threadIdx.x;
    if (e >= NE) return;
    int d = dst[e];
    int pos = atomicAdd(&cursor[d], 1);
    col[pos] = src[e];
}

// ---------------- mean aggregation (warp per node, fp16, 8x MLP) -------------
__global__ void k_agg(const __half* __restrict__ h16,
                      const int* __restrict__ rowptr,
                      const int* __restrict__ deg,
                      const int* __restrict__ col,
                      __half* __restrict__ mean16) {
    int w    = (blockIdx.x * blockDim.x + threadIdx.x) >> 5;
    int lane = threadIdx.x & 31;
    if (w >= NN) return;
    int start = rowptr[w];
    int n     = deg[w];
    float4 acc = make_float4(0.f, 0.f, 0.f, 0.f);
    const uint2* hp = (const uint2*)h16;
    int j = 0;
    for (; j + 8 <= n; j += 8) {
        int sidx[8];
#pragma unroll
        for (int u = 0; u < 8; u++) sidx[u] = col[start + j + u];
        uint2 rv[8];
#pragma unroll
        for (int u = 0; u < 8; u++) rv[u] = hp[(long)sidx[u] * 32 + lane];
#pragma unroll
        for (int u = 0; u < 8; u++) {
            float2 a = __half22float2(*(const __half2*)&rv[u].x);
            float2 b = __half22float2(*(const __half2*)&rv[u].y);
            acc.x += a.x; acc.y += a.y; acc.z += b.x; acc.w += b.y;
        }
    }
    for (; j < n; j++) {
        int s = col[start + j];
        uint2 raw = hp[(long)s * 32 + lane];
        float2 a = __half22float2(*(const __half2*)&raw.x);
        float2 b = __half22float2(*(const __half2*)&raw.y);
        acc.x += a.x; acc.y += a.y; acc.z += b.x; acc.w += b.y;
    }
    float inv = 1.0f / fmaxf((float)n, 1.0f);
    __half2 p0 = __floats2half2_rn(acc.x * inv, acc.y * inv);
    __half2 p1 = __floats2half2_rn(acc.z * inv, acc.w * inv);
    uint2 pk = make_uint2(*(uint32_t*)&p0, *(uint32_t*)&p1);
    *(uint2*)&mean16[(long)w * 128 + lane * 4] = pk;
}

// ---------------- mma.sync fp16 GEMM (single-term, exact fp16 A) -------------
#define APITCH 40                      // halfwords per row
#define PLANE  (128 * APITCH * 2)      // 10240 bytes

__global__ void __launch_bounds__(256, 1)
k_gemm_mma(const __half* __restrict__ Mean16, const __half* __restrict__ H16,
           const uint2* __restrict__ Bf, const float* __restrict__ bias,
           __half* __restrict__ outh, int do_relu) {
    __shared__ __align__(16) uint8_t sA[2][PLANE];

    int tid  = threadIdx.x;
    int wid  = tid >> 5;
    int lane = tid & 31;
    int wm   = wid & 3;
    int wn   = wid >> 2;
    int gid  = lane >> 2, tig = lane & 3;
    int row0 = blockIdx.x * 128;

    int laneRow = lane & 15;
    int laneKo  = (lane >> 4) * 8;

    uint32_t sbase = su32(&sA[0][0]);

    float acc[2][8][4];
#pragma unroll
    for (int mt = 0; mt < 2; mt++)
#pragma unroll
        for (int nt = 0; nt < 8; nt++)
#pragma unroll
            for (int j = 0; j < 4; j++) acc[mt][nt][j] = 0.f;

    const uint4 z4 = make_uint4(0u, 0u, 0u, 0u);
    int srow = tid >> 1;
    int sseg = tid & 1;

    // stage chunk 0
    {
        int gr = row0 + srow;
        uint4 v0 = z4, v1 = z4;
        if (gr < NN) {
            const uint4* src = (const uint4*)&Mean16[(long)gr * 128 + sseg * 16];
            v0 = src[0];
            v1 = src[1];
        }
        int off = srow * (APITCH * 2) + sseg * 32;
        *(uint4*)&sA[0][off]      = v0;
        *(uint4*)&sA[0][off + 16] = v1;
    }

#pragma unroll 1
    for (int c = 0; c < 8; ++c) {
        __syncthreads();

        uint4 p0 = z4, p1 = z4;
        if (c < 7) {
            const __half* Asrc = (c + 1 < 4) ? Mean16 : H16;
            int bk = ((c + 1) & 3) * 32;
            int gr = row0 + srow;
            if (gr < NN) {
                const uint4* src = (const uint4*)&Asrc[(long)gr * 128 + bk + sseg * 16];
                p0 = src[0];
                p1 = src[1];
            }
        }

        uint32_t aBase = sbase + (uint32_t)((c & 1) * PLANE);
#pragma unroll
        for (int ks = 0; ks < 2; ks++) {
            int s = c * 2 + ks;
            uint32_t af[2][4];
#pragma unroll
            for (int mt = 0; mt < 2; mt++) {
                uint32_t addr = aBase
                    + (uint32_t)((wm * 32 + mt * 16 + laneRow) * (APITCH * 2)
                                 + (ks * 16 + laneKo) * 2);
                LDSM4(af[mt], addr);
            }
            uint2 bfr[8];
#pragma unroll
            for (int nt = 0; nt < 8; nt++)
                bfr[nt] = __ldg(&Bf[(s * 16 + wn * 8 + nt) * 32 + lane]);
#pragma unroll
            for (int nt = 0; nt < 8; nt++) {
                uint32_t bb[2] = {bfr[nt].x, bfr[nt].y};
#pragma unroll
                for (int mt = 0; mt < 2; mt++)
                    MMA_F16(acc[mt][nt], af[mt], bb);
            }
        }

        if (c < 7) {
            int nb = (c + 1) & 1;
            int off = srow * (APITCH * 2) + sseg * 32;
            *(uint4*)&sA[nb][off]      = p0;
            *(uint4*)&sA[nb][off + 16] = p1;
        }
    }

    // ---- epilogue: fp16 out ----
#pragma unroll
    for (int mt = 0; mt < 2; mt++) {
        int r0 = row0 + wm * 32 + mt * 16 + gid;
        int r1 = r0 + 8;
#pragma unroll
        for (int nt = 0; nt < 8; nt++) {
            int cbase = wn * 64 + nt * 8 + tig * 2;
            float bx = __ldg(&bias[cbase]);
            float by = __ldg(&bias[cbase + 1]);
            float2 v0 = make_float2(acc[mt][nt][0] + bx, acc[mt][nt][1] + by);
            float2 v1 = make_float2(acc[mt][nt][2] + bx, acc[mt][nt][3] + by);
            if (do_relu) {
                v0.x = fmaxf(v0.x, 0.f); v0.y = fmaxf(v0.y, 0.f);
                v1.x = fmaxf(v1.x, 0.f); v1.y = fmaxf(v1.y, 0.f);
            }
            __half2 h0p = __floats2half2_rn(v0.x, v0.y);
            __half2 h1p = __floats2half2_rn(v1.x, v1.y);
            if (r0 < NN) *(uint32_t*)&outh[(long)r0 * 128 + cbase] = *(uint32_t*)&h0p;
            if (r1 < NN) *(uint32_t*)&outh[(long)r1 * 128 + cbase] = *(uint32_t*)&h1p;
        }
    }
}

// ---------------- edge-wise dot product (fp16 gather) -------------------------
__global__ void k_edgedot(const __half* __restrict__ h16,
                          const int* __restrict__ eli,
                          float* __restrict__ out) {
    int w    = (blockIdx.x * blockDim.x + threadIdx.x) >> 5;
    int lane = threadIdx.x & 31;
    if (w >= NL) return;
    int s = eli[w];
    int d = eli[NL + w];
    const uint2* hp = (const uint2*)h16;
    uint2 ra = hp[(long)s * 32 + lane];
    uint2 rb = hp[(long)d * 32 + lane];
    float2 a0 = __half22float2(*(const __half2*)&ra.x);
    float2 a1 = __half22float2(*(const __half2*)&ra.y);
    float2 b0 = __half22float2(*(const __half2*)&rb.x);
    float2 b1 = __half22float2(*(const __half2*)&rb.y);
    float sum = a0.x * b0.x + a0.y * b0.y + a1.x * b1.x + a1.y * b1.y;
#pragma unroll
    for (int o = 16; o; o >>= 1) sum += __shfl_xor_sync(0xffffffffu, sum, o);
    if (lane == 0) out[w] = sum;
}

// ---------------- launch ------------------------------------------------------
extern "C" void kernel_launch(void* const* d_in, const int* in_sizes, int n_in,
                              void* d_out, int out_size) {
    const int*   n_id = (const int*)d_in[0];
    const float* x    = (const float*)d_in[1];
    const int*   ei   = (const int*)d_in[2];
    const int*   eli  = (const int*)d_in[3];
    const float* emb  = (const float*)d_in[4];
    const float* W1l  = (const float*)d_in[5];
    const float* W1r  = (const float*)d_in[6];
    const float* b1   = (const float*)d_in[7];
    const float* W2l  = (const float*)d_in[8];
    const float* W2r  = (const float*)d_in[9];
    const float* b2   = (const float*)d_in[10];
    float* out = (float*)d_out;

    __half *h0h, *mean16, *h1h, *h2h;
    int *deg, *rowptr, *cursor, *col, *bsums;
    uint2* bfrag;
    cudaGetSymbolAddress((void**)&h0h,    g_h0h);
    cudaGetSymbolAddress((void**)&mean16, g_mean16);
    cudaGetSymbolAddress((void**)&h1h,    g_h1h);
    cudaGetSymbolAddress((void**)&h2h,    g_h2h);
    cudaGetSymbolAddress((void**)&deg,    g_deg);
    cudaGetSymbolAddress((void**)&rowptr, g_rowptr);
    cudaGetSymbolAddress((void**)&cursor, g_cursor);
    cudaGetSymbolAddress((void**)&col,    g_col);
    cudaGetSymbolAddress((void**)&bsums,  g_bsums);
    cudaGetSymbolAddress((void**)&bfrag,  g_bfrag);

    const int NB_SCAN = (NN + 1023) / 1024;  // 49

    cudaMemsetAsync(deg, 0, sizeof(int) * NN);

    k_pre<<<CB + DB + WB, 256>>>(n_id, x, emb, ei + NE, W1l, W1r, W2l, W2r,
                                 h0h, deg, bfrag);
    k_scan1<<<NB_SCAN, 1024>>>(deg, rowptr, bsums);
    k_scan3f<<<NB_SCAN, 1024>>>(rowptr, bsums, NB_SCAN, cursor);
    k_fill<<<(NE + 255) / 256, 256>>>(ei, ei + NE, cursor, col);

    const int GB = (NN + 127) / 128;  // 391

    // layer 1
    k_agg<<<(NN * 32 + 255) / 256, 256>>>(h0h, rowptr, deg, col, mean16);
    k_gemm_mma<<<GB, 256>>>(mean16, h0h, bfrag, b1, h1h, 1);

    // layer 2
    k_agg<<<(NN * 32 + 255) / 256, 256>>>(h1h, rowptr, deg, col, mean16);
    k_gemm_mma<<<GB, 256>>>(mean16, h1h, bfrag + 8192, b2, h2h, 0);

    // classifier
    k_edgedot<<<(NL * 32 + 255) / 256, 256>>>(h2h, eli, out);
}